// round 1
// baseline (speedup 1.0000x reference)
#include <cuda_runtime.h>
#include <math.h>

// Problem constants
#define MB  256                // batch m
#define S   128                // seq len
#define C   256                // channels
#define H   8                  // heads
#define D   32                 // head dim
#define MROWS (MB*S)           // 32768 flattened rows
#define C2  (2*C)              // 512
#define NHB (MB*H)             // 2048 (n,h) pairs
#define SSQ (S*S)              // 16384

// ---------------- scratch (device globals; no runtime allocation) ----------
__device__ float g_q [MROWS*C];
__device__ float g_k [MROWS*C];
__device__ float g_v [MROWS*C];
__device__ float g_e [NHB*SSQ];     // energy -> attn (in place)
__device__ float g_o [MROWS*C];
__device__ float g_x1[MROWS*C];
__device__ float g_t2[MROWS*C2];    // FFN hidden GEMM output
__device__ float g_psum[131072];
__device__ float g_psq [131072];
__device__ float g_scale[C2];
__device__ float g_shift[C2];
__device__ float g_scale_pe[SSQ];
__device__ float g_shift_pe[SSQ];

// ---------------- BN stats: deterministic 2-stage reduction ----------------
// Stage 1: per-(row-chunk, channel) partial sum / sumsq. Coalesced: thread=channel.
__global__ void bn_partial(const float* __restrict__ X, int Cdim, int rowsPerBlock,
                           float* __restrict__ psum, float* __restrict__ psq) {
    int c = blockIdx.x * blockDim.x + threadIdx.x;   // channel
    int r0 = blockIdx.y * rowsPerBlock;
    float s = 0.f, q = 0.f;
    const float* Xp = X + (size_t)r0 * Cdim + c;
    for (int i = 0; i < rowsPerBlock; i++) {
        float v = Xp[(size_t)i * Cdim];
        s += v; q += v * v;
    }
    psum[(size_t)blockIdx.y * Cdim + c] = s;
    psq [(size_t)blockIdx.y * Cdim + c] = q;
}

// Stage 2: fold partials -> scale/shift for affine BN (y = x*scale + shift).
__global__ void bn_finalize(const float* __restrict__ psum, const float* __restrict__ psq,
                            int Cdim, int nparts, float invM,
                            const float* __restrict__ g, const float* __restrict__ b,
                            float* __restrict__ scale, float* __restrict__ shift) {
    int c = blockIdx.x * blockDim.x + threadIdx.x;
    float s = 0.f, q = 0.f;
    for (int p = 0; p < nparts; p++) {
        s += psum[(size_t)p * Cdim + c];
        q += psq [(size_t)p * Cdim + c];
    }
    float mean = s * invM;
    float var  = q * invM - mean * mean;
    float sc   = g[c] * rsqrtf(var + 1e-5f);
    scale[c] = sc;
    shift[c] = b[c] - mean * sc;
}

// ---------------- Tiled GEMM: Cout[M,N] = op(A[M,K]) @ B[N,K]^T (+epilogue) --
// op(A): optional per-K-channel affine (fused BN) + optional relu.
// 64x64 tile, BK=16, 256 threads, 4x4 per thread.
template<bool AFFINE, bool RELU, bool BIAS, bool RES>
__global__ void gemm_nt(const float* __restrict__ A, const float* __restrict__ B,
                        float* __restrict__ Cout,
                        const float* __restrict__ scale, const float* __restrict__ shift,
                        const float* __restrict__ bias,  const float* __restrict__ res,
                        int M_, int N_, int K_) {
    __shared__ __align__(16) float As[16][68];
    __shared__ __align__(16) float Bs[16][68];
    int t  = threadIdx.x;
    int ty = t >> 4, tx = t & 15;
    int lj = t & 15, lr = t >> 4;             // loader: k-col, row base
    int row0 = blockIdx.y * 64, col0 = blockIdx.x * 64;
    float acc[4][4] = {};

    for (int kt = 0; kt < K_; kt += 16) {
        #pragma unroll
        for (int p = 0; p < 4; p++) {
            int r = p * 16 + lr;
            float a = A[(size_t)(row0 + r) * K_ + kt + lj];
            if (AFFINE) {
                a = a * scale[kt + lj] + shift[kt + lj];
                if (RELU) a = fmaxf(a, 0.f);
            }
            As[lj][r] = a;
            Bs[lj][r] = B[(size_t)(col0 + r) * K_ + kt + lj];
        }
        __syncthreads();
        #pragma unroll
        for (int k = 0; k < 16; k++) {
            float4 a4 = *(const float4*)&As[k][ty * 4];
            float4 b4 = *(const float4*)&Bs[k][tx * 4];
            float a[4] = {a4.x, a4.y, a4.z, a4.w};
            float b[4] = {b4.x, b4.y, b4.z, b4.w};
            #pragma unroll
            for (int i = 0; i < 4; i++)
                #pragma unroll
                for (int j = 0; j < 4; j++)
                    acc[i][j] += a[i] * b[j];
        }
        __syncthreads();
    }
    #pragma unroll
    for (int i = 0; i < 4; i++) {
        int r = row0 + ty * 4 + i;
        #pragma unroll
        for (int j = 0; j < 4; j++) {
            int cc = col0 + tx * 4 + j;
            float v = acc[i][j];
            if (BIAS) v += bias[cc];
            if (RES)  v += res[(size_t)r * N_ + cc];
            Cout[(size_t)r * N_ + cc] = v;
        }
    }
}

// ---------------- energy[n,h,q,k] = sum_d q[n,q,h,d]*k[n,k,h,d] -------------
// one block per (n,h); 128x128 output, K=32; 256 threads, 8x8 per thread.
__global__ void energy_kernel(const float* __restrict__ Q, const float* __restrict__ Kt,
                              float* __restrict__ E) {
    int nh = blockIdx.x;
    int n = nh >> 3, h = nh & 7;
    __shared__ __align__(16) float qs[32][132];
    __shared__ __align__(16) float ks[32][132];
    int t = threadIdx.x;
    int dd = t & 31, sb = t >> 5;
    const float* qb = Q + ((size_t)(n * S) * H + h) * D;
    const float* kb = Kt + ((size_t)(n * S) * H + h) * D;
    #pragma unroll
    for (int p = 0; p < 16; p++) {
        int s = p * 8 + sb;
        qs[dd][s] = qb[(size_t)s * (H * D) + dd];
        ks[dd][s] = kb[(size_t)s * (H * D) + dd];
    }
    __syncthreads();
    int ty = t >> 4, tx = t & 15;
    float acc[8][8] = {};
    #pragma unroll
    for (int k = 0; k < 32; k++) {
        float4 a0 = *(const float4*)&qs[k][ty * 8];
        float4 a1 = *(const float4*)&qs[k][ty * 8 + 4];
        float4 b0 = *(const float4*)&ks[k][tx * 8];
        float4 b1 = *(const float4*)&ks[k][tx * 8 + 4];
        float a[8] = {a0.x,a0.y,a0.z,a0.w,a1.x,a1.y,a1.z,a1.w};
        float b[8] = {b0.x,b0.y,b0.z,b0.w,b1.x,b1.y,b1.z,b1.w};
        #pragma unroll
        for (int i = 0; i < 8; i++)
            #pragma unroll
            for (int j = 0; j < 8; j++)
                acc[i][j] += a[i] * b[j];
    }
    float* eb = E + (size_t)nh * SSQ;
    #pragma unroll
    for (int i = 0; i < 8; i++)
        #pragma unroll
        for (int j = 0; j < 8; j++)
            eb[(size_t)(ty * 8 + i) * S + tx * 8 + j] = acc[i][j];
}

// ---------------- fused BN(affine) + /sqrt(C) + softmax over last dim ------
// one warp per row of 128; in-place on energy buffer.
__global__ void softmax_kernel(float* __restrict__ E,
                               const float* __restrict__ scale,
                               const float* __restrict__ shift) {
    int warp = threadIdx.x >> 5, lane = threadIdx.x & 31;
    int row = blockIdx.x * 8 + warp;          // (n*H+h)*S + qi
    int qi = row & (S - 1);
    float* e = E + (size_t)row * S;
    const float* sc = scale + qi * S;
    const float* sh = shift + qi * S;
    float v[4];
    float mx = -INFINITY;
    #pragma unroll
    for (int i = 0; i < 4; i++) {
        int ki = i * 32 + lane;
        v[i] = (e[ki] * sc[ki] + sh[ki]) * 0.0625f;   // /sqrt(256)
        mx = fmaxf(mx, v[i]);
    }
    #pragma unroll
    for (int off = 16; off > 0; off >>= 1)
        mx = fmaxf(mx, __shfl_xor_sync(0xffffffffu, mx, off));
    float sum = 0.f;
    #pragma unroll
    for (int i = 0; i < 4; i++) { v[i] = __expf(v[i] - mx); sum += v[i]; }
    #pragma unroll
    for (int off = 16; off > 0; off >>= 1)
        sum += __shfl_xor_sync(0xffffffffu, sum, off);
    float inv = 1.f / sum;
    #pragma unroll
    for (int i = 0; i < 4; i++)
        e[i * 32 + lane] = v[i] * inv;
}

// ---------------- o[n,q,h,d] = sum_l attn[n,h,q,l] * v[n,l,h,d] ------------
// one block per (n,h); 128x32 output; 256 threads, 4x4 per thread.
__global__ void av_kernel(const float* __restrict__ A, const float* __restrict__ V,
                          float* __restrict__ O) {
    int nh = blockIdx.x;
    int n = nh >> 3, h = nh & 7;
    __shared__ float as_[128][33];
    __shared__ float vs[32][33];
    int t = threadIdx.x;
    const float* ab = A + (size_t)nh * SSQ;
    const float* vb = V + ((size_t)(n * S) * H + h) * D;
    int col = t & 31, rb = t >> 5;
    int ty = t >> 3, tx = t & 7;
    float acc[4][4] = {};
    for (int lc = 0; lc < 4; lc++) {
        int l0 = lc * 32;
        #pragma unroll
        for (int p = 0; p < 16; p++) {
            int r = p * 8 + rb;
            as_[r][col] = ab[(size_t)r * S + l0 + col];
        }
        #pragma unroll
        for (int p = 0; p < 4; p++) {
            int r = p * 8 + rb;
            vs[r][col] = vb[(size_t)(l0 + r) * (H * D) + col];
        }
        __syncthreads();
        #pragma unroll
        for (int l = 0; l < 32; l++) {
            float a[4], b[4];
            #pragma unroll
            for (int i = 0; i < 4; i++) a[i] = as_[ty * 4 + i][l];
            #pragma unroll
            for (int j = 0; j < 4; j++) b[j] = vs[l][tx * 4 + j];
            #pragma unroll
            for (int i = 0; i < 4; i++)
                #pragma unroll
                for (int j = 0; j < 4; j++)
                    acc[i][j] += a[i] * b[j];
        }
        __syncthreads();
    }
    float* ob = O + ((size_t)(n * S) * H + h) * D;
    #pragma unroll
    for (int i = 0; i < 4; i++)
        #pragma unroll
        for (int j = 0; j < 4; j++)
            ob[(size_t)(ty * 4 + i) * (H * D) + tx * 4 + j] = acc[i][j];
}

// ---------------------------------------------------------------------------
extern "C" void kernel_launch(void* const* d_in, const int* in_sizes, int n_in,
                              void* d_out, int out_size) {
    const float* x    = (const float*)d_in[0];
    const float* g_n  = (const float*)d_in[1];
    const float* b_n  = (const float*)d_in[2];
    const float* Wq   = (const float*)d_in[3];
    const float* Wk   = (const float*)d_in[4];
    const float* Wv   = (const float*)d_in[5];
    const float* Wo   = (const float*)d_in[6];
    const float* bo   = (const float*)d_in[7];
    const float* g_pe = (const float*)d_in[8];
    const float* b_pe = (const float*)d_in[9];
    const float* g0   = (const float*)d_in[10];
    const float* b0   = (const float*)d_in[11];
    const float* W0   = (const float*)d_in[12];
    const float* g1   = (const float*)d_in[13];
    const float* b1   = (const float*)d_in[14];
    const float* W1   = (const float*)d_in[15];
    float* out = (float*)d_out;

    float *q, *k, *v, *e, *o, *x1, *t2, *psum, *psq, *sc, *sh, *scpe, *shpe;
    cudaGetSymbolAddress((void**)&q,    g_q);
    cudaGetSymbolAddress((void**)&k,    g_k);
    cudaGetSymbolAddress((void**)&v,    g_v);
    cudaGetSymbolAddress((void**)&e,    g_e);
    cudaGetSymbolAddress((void**)&o,    g_o);
    cudaGetSymbolAddress((void**)&x1,   g_x1);
    cudaGetSymbolAddress((void**)&t2,   g_t2);
    cudaGetSymbolAddress((void**)&psum, g_psum);
    cudaGetSymbolAddress((void**)&psq,  g_psq);
    cudaGetSymbolAddress((void**)&sc,   g_scale);
    cudaGetSymbolAddress((void**)&sh,   g_shift);
    cudaGetSymbolAddress((void**)&scpe, g_scale_pe);
    cudaGetSymbolAddress((void**)&shpe, g_shift_pe);

    // --- BN over C on x -> scale/shift (fused into QKV GEMM loads) ---
    bn_partial<<<dim3(1, 128), 256>>>(x, C, 256, psum, psq);
    bn_finalize<<<1, 256>>>(psum, psq, C, 128, 1.f / MROWS, g_n, b_n, sc, sh);

    // --- q/k/v = bn(x) @ W{q,k,v}^T ---
    dim3 gqkv(C / 64, MROWS / 64);
    gemm_nt<true, false, false, false><<<gqkv, 256>>>(x, Wq, q, sc, sh, nullptr, nullptr, MROWS, C, C);
    gemm_nt<true, false, false, false><<<gqkv, 256>>>(x, Wk, k, sc, sh, nullptr, nullptr, MROWS, C, C);
    gemm_nt<true, false, false, false><<<gqkv, 256>>>(x, Wv, v, sc, sh, nullptr, nullptr, MROWS, C, C);

    // --- energy ---
    energy_kernel<<<NHB, 256>>>(q, k, e);

    // --- BN over S*S positions on energy ---
    bn_partial<<<dim3(SSQ / 256, 8), 256>>>(e, SSQ, 256, psum, psq);
    bn_finalize<<<SSQ / 256, 256>>>(psum, psq, SSQ, 8, 1.f / NHB, g_pe, b_pe, scpe, shpe);

    // --- fused BN + scale + softmax (in place on e) ---
    softmax_kernel<<<(NHB * S) / 8, 256>>>(e, scpe, shpe);

    // --- o = attn @ v ---
    av_kernel<<<NHB, 256>>>(e, v, o);

    // --- x1 = o @ Wo^T + bo + x ---
    gemm_nt<false, false, true, true><<<gqkv, 256>>>(o, Wo, x1, nullptr, nullptr, bo, x, MROWS, C, C);

    // --- FFN: BN0 -> relu -> W0 ---
    bn_partial<<<dim3(1, 128), 256>>>(x1, C, 256, psum, psq);
    bn_finalize<<<1, 256>>>(psum, psq, C, 128, 1.f / MROWS, g0, b0, sc, sh);
    dim3 gffn0(C2 / 64, MROWS / 64);
    gemm_nt<true, true, false, false><<<gffn0, 256>>>(x1, W0, t2, sc, sh, nullptr, nullptr, MROWS, C2, C);

    // --- BN1 -> relu -> W1 -> + x1 (final output) ---
    bn_partial<<<dim3(2, 128), 256>>>(t2, C2, 256, psum, psq);
    bn_finalize<<<2, 256>>>(psum, psq, C2, 128, 1.f / MROWS, g1, b1, sc, sh);
    gemm_nt<true, true, false, true><<<gqkv, 256>>>(t2, W1, out, sc, sh, nullptr, x1, MROWS, C, C2);
}

// round 2
// speedup vs baseline: 1.2013x; 1.2013x over previous
#include <cuda_runtime.h>
#include <math.h>

// Problem constants
#define MB  256
#define S   128
#define C   256
#define H   8
#define D   32
#define MROWS (MB*S)           // 32768
#define C2  (2*C)              // 512
#define NHB (MB*H)             // 2048
#define SSQ (S*S)              // 16384

// ---------------- scratch (device globals) ----------------
__device__ float g_q [MROWS*C];
__device__ float g_k [MROWS*C];
__device__ float g_v [MROWS*C];
__device__ float g_e [NHB*SSQ];
__device__ float g_o [MROWS*C];
__device__ float g_x1[MROWS*C];
__device__ float g_t2[MROWS*C2];
__device__ float g_psum[131072];
__device__ float g_psq [131072];
__device__ float g_scale[C2];
__device__ float g_shift[C2];
__device__ float g_scale_pe[SSQ];
__device__ float g_shift_pe[SSQ];

// ---------------- packed fp32x2 helpers (Blackwell FFMA2) ----------------
typedef unsigned long long u64;

__device__ __forceinline__ u64 pack2(float x) {
    u64 r;
    unsigned u = __float_as_uint(x);
    asm("mov.b64 %0, {%1, %1};" : "=l"(r) : "r"(u));
    return r;
}
__device__ __forceinline__ void ffma2(u64& d, u64 a, u64 b) {
    asm("fma.rn.f32x2 %0, %1, %2, %0;" : "+l"(d) : "l"(a), "l"(b));
}
__device__ __forceinline__ float lo32(u64 v) { return __uint_as_float((unsigned)v); }
__device__ __forceinline__ float hi32(u64 v) { return __uint_as_float((unsigned)(v >> 32)); }

// ---------------- BN stats: deterministic 2-stage reduction ----------------
__global__ void bn_partial(const float* __restrict__ X, int Cdim, int rowsPerBlock,
                           float* __restrict__ psum, float* __restrict__ psq) {
    int c = blockIdx.x * blockDim.x + threadIdx.x;
    int r0 = blockIdx.y * rowsPerBlock;
    float s = 0.f, q = 0.f;
    const float* Xp = X + (size_t)r0 * Cdim + c;
    for (int i = 0; i < rowsPerBlock; i++) {
        float v = Xp[(size_t)i * Cdim];
        s += v; q += v * v;
    }
    psum[(size_t)blockIdx.y * Cdim + c] = s;
    psq [(size_t)blockIdx.y * Cdim + c] = q;
}

__global__ void bn_finalize(const float* __restrict__ psum, const float* __restrict__ psq,
                            int Cdim, int nparts, float invM,
                            const float* __restrict__ g, const float* __restrict__ b,
                            float* __restrict__ scale, float* __restrict__ shift) {
    int c = blockIdx.x * blockDim.x + threadIdx.x;
    float s = 0.f, q = 0.f;
    for (int p = 0; p < nparts; p++) {
        s += psum[(size_t)p * Cdim + c];
        q += psq [(size_t)p * Cdim + c];
    }
    float mean = s * invM;
    float var  = q * invM - mean * mean;
    float sc   = g[c] * rsqrtf(var + 1e-5f);
    scale[c] = sc;
    shift[c] = b[c] - mean * sc;
}

// ---------------- 128x128 tiled GEMM with FFMA2 inner loop ------------------
// Cout[M,N] = op(A[M,K]) @ B[N,K]^T (+epilogue). op: per-K affine (+relu).
// 256 threads, 8x8 per thread (accumulated as 8x4 f32x2 pairs), BK=16,
// double-buffered smem.
template<bool AFFINE, bool RELU, bool BIAS, bool RES>
__global__ void __launch_bounds__(256, 2)
gemm128(const float* __restrict__ A, const float* __restrict__ B,
        float* __restrict__ Cout,
        const float* __restrict__ scale, const float* __restrict__ shift,
        const float* __restrict__ bias,  const float* __restrict__ res,
        int M_, int N_, int K_) {
    __shared__ __align__(16) float As[2][16][132];
    __shared__ __align__(16) float Bs[2][16][132];

    const int t = threadIdx.x;
    const int ty = t >> 4, tx = t & 15;
    const int row0 = blockIdx.y * 128, col0 = blockIdx.x * 128;

    u64 acc[8][4];
    #pragma unroll
    for (int i = 0; i < 8; i++)
        #pragma unroll
        for (int j = 0; j < 4; j++) acc[i][j] = 0ull;

    float4 ra[2], rb[2];

    // global -> regs for k-tile starting at k0 (affine applied here)
    auto load_tiles = [&](int k0) {
        #pragma unroll
        for (int i = 0; i < 2; i++) {
            int f  = t + i * 256;
            int r  = f >> 2;
            int kq = (f & 3) * 4;
            float4 va = *(const float4*)&A[(size_t)(row0 + r) * K_ + k0 + kq];
            if (AFFINE) {
                va.x = va.x * scale[k0+kq+0] + shift[k0+kq+0];
                va.y = va.y * scale[k0+kq+1] + shift[k0+kq+1];
                va.z = va.z * scale[k0+kq+2] + shift[k0+kq+2];
                va.w = va.w * scale[k0+kq+3] + shift[k0+kq+3];
                if (RELU) {
                    va.x = fmaxf(va.x, 0.f); va.y = fmaxf(va.y, 0.f);
                    va.z = fmaxf(va.z, 0.f); va.w = fmaxf(va.w, 0.f);
                }
            }
            ra[i] = va;
            rb[i] = *(const float4*)&B[(size_t)(col0 + r) * K_ + k0 + kq];
        }
    };
    // regs -> smem buffer
    auto store_tiles = [&](int buf) {
        #pragma unroll
        for (int i = 0; i < 2; i++) {
            int f  = t + i * 256;
            int r  = f >> 2;
            int kq = (f & 3) * 4;
            As[buf][kq+0][r] = ra[i].x; As[buf][kq+1][r] = ra[i].y;
            As[buf][kq+2][r] = ra[i].z; As[buf][kq+3][r] = ra[i].w;
            Bs[buf][kq+0][r] = rb[i].x; Bs[buf][kq+1][r] = rb[i].y;
            Bs[buf][kq+2][r] = rb[i].z; Bs[buf][kq+3][r] = rb[i].w;
        }
    };

    load_tiles(0);
    store_tiles(0);
    __syncthreads();

    const int nkt = K_ >> 4;
    for (int kt = 0; kt < nkt; kt++) {
        int buf = kt & 1;
        if (kt + 1 < nkt) load_tiles((kt + 1) * 16);

        #pragma unroll
        for (int k = 0; k < 16; k++) {
            float4 a0 = *(const float4*)&As[buf][k][ty * 8];
            float4 a1 = *(const float4*)&As[buf][k][ty * 8 + 4];
            ulonglong2 b0 = *(const ulonglong2*)&Bs[buf][k][tx * 8];
            ulonglong2 b1 = *(const ulonglong2*)&Bs[buf][k][tx * 8 + 4];
            u64 bb[4] = {b0.x, b0.y, b1.x, b1.y};
            float a[8] = {a0.x, a0.y, a0.z, a0.w, a1.x, a1.y, a1.z, a1.w};
            #pragma unroll
            for (int i = 0; i < 8; i++) {
                u64 ad = pack2(a[i]);
                #pragma unroll
                for (int j = 0; j < 4; j++) ffma2(acc[i][j], ad, bb[j]);
            }
        }

        if (kt + 1 < nkt) store_tiles(buf ^ 1);
        __syncthreads();
    }

    // epilogue
    #pragma unroll
    for (int i = 0; i < 8; i++) {
        int r = row0 + ty * 8 + i;
        float vout[8];
        #pragma unroll
        for (int j = 0; j < 4; j++) {
            vout[2*j]   = lo32(acc[i][j]);
            vout[2*j+1] = hi32(acc[i][j]);
        }
        int cbase = col0 + tx * 8;
        #pragma unroll
        for (int j = 0; j < 8; j++) {
            int cc = cbase + j;
            if (BIAS) vout[j] += bias[cc];
            if (RES)  vout[j] += res[(size_t)r * N_ + cc];
        }
        *(float4*)&Cout[(size_t)r * N_ + cbase]     = make_float4(vout[0], vout[1], vout[2], vout[3]);
        *(float4*)&Cout[(size_t)r * N_ + cbase + 4] = make_float4(vout[4], vout[5], vout[6], vout[7]);
    }
}

// ---------------- energy[n,h,q,k] = sum_d q[n,q,h,d]*k[n,k,h,d] -------------
__global__ void energy_kernel(const float* __restrict__ Q, const float* __restrict__ Kt,
                              float* __restrict__ E) {
    int nh = blockIdx.x;
    int n = nh >> 3, h = nh & 7;
    __shared__ __align__(16) float qs[32][132];
    __shared__ __align__(16) float ks[32][132];
    int t = threadIdx.x;
    int dd = t & 31, sb = t >> 5;
    const float* qb = Q + ((size_t)(n * S) * H + h) * D;
    const float* kb = Kt + ((size_t)(n * S) * H + h) * D;
    #pragma unroll
    for (int p = 0; p < 16; p++) {
        int s = p * 8 + sb;
        qs[dd][s] = qb[(size_t)s * (H * D) + dd];
        ks[dd][s] = kb[(size_t)s * (H * D) + dd];
    }
    __syncthreads();
    int ty = t >> 4, tx = t & 15;
    u64 acc[8][4];
    #pragma unroll
    for (int i = 0; i < 8; i++)
        #pragma unroll
        for (int j = 0; j < 4; j++) acc[i][j] = 0ull;
    #pragma unroll
    for (int k = 0; k < 32; k++) {
        float4 a0 = *(const float4*)&qs[k][ty * 8];
        float4 a1 = *(const float4*)&qs[k][ty * 8 + 4];
        ulonglong2 b0 = *(const ulonglong2*)&ks[k][tx * 8];
        ulonglong2 b1 = *(const ulonglong2*)&ks[k][tx * 8 + 4];
        u64 bb[4] = {b0.x, b0.y, b1.x, b1.y};
        float a[8] = {a0.x, a0.y, a0.z, a0.w, a1.x, a1.y, a1.z, a1.w};
        #pragma unroll
        for (int i = 0; i < 8; i++) {
            u64 ad = pack2(a[i]);
            #pragma unroll
            for (int j = 0; j < 4; j++) ffma2(acc[i][j], ad, bb[j]);
        }
    }
    float* eb = E + (size_t)nh * SSQ;
    #pragma unroll
    for (int i = 0; i < 8; i++) {
        float vout[8];
        #pragma unroll
        for (int j = 0; j < 4; j++) {
            vout[2*j]   = lo32(acc[i][j]);
            vout[2*j+1] = hi32(acc[i][j]);
        }
        *(float4*)&eb[(size_t)(ty * 8 + i) * S + tx * 8]     = make_float4(vout[0], vout[1], vout[2], vout[3]);
        *(float4*)&eb[(size_t)(ty * 8 + i) * S + tx * 8 + 4] = make_float4(vout[4], vout[5], vout[6], vout[7]);
    }
}

// ---------------- fused BN(affine) + /sqrt(C) + softmax ---------------------
__global__ void softmax_kernel(float* __restrict__ E,
                               const float* __restrict__ scale,
                               const float* __restrict__ shift) {
    int warp = threadIdx.x >> 5, lane = threadIdx.x & 31;
    int row = blockIdx.x * 8 + warp;
    int qi = row & (S - 1);
    float* e = E + (size_t)row * S;
    const float* sc = scale + qi * S;
    const float* sh = shift + qi * S;
    float v[4];
    float mx = -INFINITY;
    #pragma unroll
    for (int i = 0; i < 4; i++) {
        int ki = i * 32 + lane;
        v[i] = (e[ki] * sc[ki] + sh[ki]) * 0.0625f;
        mx = fmaxf(mx, v[i]);
    }
    #pragma unroll
    for (int off = 16; off > 0; off >>= 1)
        mx = fmaxf(mx, __shfl_xor_sync(0xffffffffu, mx, off));
    float sum = 0.f;
    #pragma unroll
    for (int i = 0; i < 4; i++) { v[i] = __expf(v[i] - mx); sum += v[i]; }
    #pragma unroll
    for (int off = 16; off > 0; off >>= 1)
        sum += __shfl_xor_sync(0xffffffffu, sum, off);
    float inv = 1.f / sum;
    #pragma unroll
    for (int i = 0; i < 4; i++)
        e[i * 32 + lane] = v[i] * inv;
}

// ---------------- o[n,q,h,d] = sum_l attn[n,h,q,l] * v[n,l,h,c] -------------
__global__ void av_kernel(const float* __restrict__ A, const float* __restrict__ V,
                          float* __restrict__ O) {
    int nh = blockIdx.x;
    int n = nh >> 3, h = nh & 7;
    __shared__ float as_[128][33];
    __shared__ float vs[32][33];
    int t = threadIdx.x;
    const float* ab = A + (size_t)nh * SSQ;
    const float* vb = V + ((size_t)(n * S) * H + h) * D;
    int col = t & 31, rb = t >> 5;
    int ty = t >> 3, tx = t & 7;
    float acc[4][4] = {};
    for (int lc = 0; lc < 4; lc++) {
        int l0 = lc * 32;
        #pragma unroll
        for (int p = 0; p < 16; p++) {
            int r = p * 8 + rb;
            as_[r][col] = ab[(size_t)r * S + l0 + col];
        }
        #pragma unroll
        for (int p = 0; p < 4; p++) {
            int r = p * 8 + rb;
            vs[r][col] = vb[(size_t)(l0 + r) * (H * D) + col];
        }
        __syncthreads();
        #pragma unroll
        for (int l = 0; l < 32; l++) {
            float a[4], b[4];
            #pragma unroll
            for (int i = 0; i < 4; i++) a[i] = as_[ty * 4 + i][l];
            #pragma unroll
            for (int j = 0; j < 4; j++) b[j] = vs[l][tx * 4 + j];
            #pragma unroll
            for (int i = 0; i < 4; i++)
                #pragma unroll
                for (int j = 0; j < 4; j++)
                    acc[i][j] += a[i] * b[j];
        }
        __syncthreads();
    }
    float* ob = O + ((size_t)(n * S) * H + h) * D;
    #pragma unroll
    for (int i = 0; i < 4; i++)
        #pragma unroll
        for (int j = 0; j < 4; j++)
            ob[(size_t)(ty * 4 + i) * (H * D) + tx * 4 + j] = acc[i][j];
}

// ---------------------------------------------------------------------------
extern "C" void kernel_launch(void* const* d_in, const int* in_sizes, int n_in,
                              void* d_out, int out_size) {
    const float* x    = (const float*)d_in[0];
    const float* g_n  = (const float*)d_in[1];
    const float* b_n  = (const float*)d_in[2];
    const float* Wq   = (const float*)d_in[3];
    const float* Wk   = (const float*)d_in[4];
    const float* Wv   = (const float*)d_in[5];
    const float* Wo   = (const float*)d_in[6];
    const float* bo   = (const float*)d_in[7];
    const float* g_pe = (const float*)d_in[8];
    const float* b_pe = (const float*)d_in[9];
    const float* g0   = (const float*)d_in[10];
    const float* b0   = (const float*)d_in[11];
    const float* W0   = (const float*)d_in[12];
    const float* g1   = (const float*)d_in[13];
    const float* b1   = (const float*)d_in[14];
    const float* W1   = (const float*)d_in[15];
    float* out = (float*)d_out;

    float *q, *k, *v, *e, *o, *x1, *t2, *psum, *psq, *sc, *sh, *scpe, *shpe;
    cudaGetSymbolAddress((void**)&q,    g_q);
    cudaGetSymbolAddress((void**)&k,    g_k);
    cudaGetSymbolAddress((void**)&v,    g_v);
    cudaGetSymbolAddress((void**)&e,    g_e);
    cudaGetSymbolAddress((void**)&o,    g_o);
    cudaGetSymbolAddress((void**)&x1,   g_x1);
    cudaGetSymbolAddress((void**)&t2,   g_t2);
    cudaGetSymbolAddress((void**)&psum, g_psum);
    cudaGetSymbolAddress((void**)&psq,  g_psq);
    cudaGetSymbolAddress((void**)&sc,   g_scale);
    cudaGetSymbolAddress((void**)&sh,   g_shift);
    cudaGetSymbolAddress((void**)&scpe, g_scale_pe);
    cudaGetSymbolAddress((void**)&shpe, g_shift_pe);

    // --- BN over C on x ---
    bn_partial<<<dim3(1, 128), 256>>>(x, C, 256, psum, psq);
    bn_finalize<<<1, 256>>>(psum, psq, C, 128, 1.f / MROWS, g_n, b_n, sc, sh);

    // --- q/k/v = bn(x) @ W{q,k,v}^T ---
    dim3 gqkv(C / 128, MROWS / 128);           // (2, 256)
    gemm128<true, false, false, false><<<gqkv, 256>>>(x, Wq, q, sc, sh, nullptr, nullptr, MROWS, C, C);
    gemm128<true, false, false, false><<<gqkv, 256>>>(x, Wk, k, sc, sh, nullptr, nullptr, MROWS, C, C);
    gemm128<true, false, false, false><<<gqkv, 256>>>(x, Wv, v, sc, sh, nullptr, nullptr, MROWS, C, C);

    // --- energy ---
    energy_kernel<<<NHB, 256>>>(q, k, e);

    // --- BN over S*S positions on energy ---
    bn_partial<<<dim3(SSQ / 256, 8), 256>>>(e, SSQ, 256, psum, psq);
    bn_finalize<<<SSQ / 256, 256>>>(psum, psq, SSQ, 8, 1.f / NHB, g_pe, b_pe, scpe, shpe);

    // --- fused BN + scale + softmax ---
    softmax_kernel<<<(NHB * S) / 8, 256>>>(e, scpe, shpe);

    // --- o = attn @ v ---
    av_kernel<<<NHB, 256>>>(e, v, o);

    // --- x1 = o @ Wo^T + bo + x ---
    gemm128<false, false, true, true><<<gqkv, 256>>>(o, Wo, x1, nullptr, nullptr, bo, x, MROWS, C, C);

    // --- FFN: BN0 -> relu -> W0 ---
    bn_partial<<<dim3(1, 128), 256>>>(x1, C, 256, psum, psq);
    bn_finalize<<<1, 256>>>(psum, psq, C, 128, 1.f / MROWS, g0, b0, sc, sh);
    dim3 gffn0(C2 / 128, MROWS / 128);         // (4, 256)
    gemm128<true, true, false, false><<<gffn0, 256>>>(x1, W0, t2, sc, sh, nullptr, nullptr, MROWS, C2, C);

    // --- BN1 -> relu -> W1 -> + x1 ---
    bn_partial<<<dim3(2, 128), 256>>>(t2, C2, 256, psum, psq);
    bn_finalize<<<2, 256>>>(psum, psq, C2, 128, 1.f / MROWS, g1, b1, sc, sh);
    gemm128<true, true, false, true><<<gqkv, 256>>>(t2, W1, out, sc, sh, nullptr, x1, MROWS, C, C2);
}

// round 4
// speedup vs baseline: 1.8985x; 1.5804x over previous
#include <cuda_runtime.h>
#include <cuda_bf16.h>
#include <math.h>
#include <stdint.h>

// Problem constants
#define MB  256
#define S   128
#define C   256
#define H   8
#define D   32
#define MROWS (MB*S)           // 32768
#define C2  (2*C)              // 512
#define NHB (MB*H)             // 2048
#define SSQ (S*S)              // 16384

// ---------------- scratch (device globals) ----------------
__device__ float g_q [MROWS*C];
__device__ float g_k [MROWS*C];
__device__ float g_v [MROWS*C];
__device__ float g_e [NHB*SSQ];
__device__ float g_o [MROWS*C];
__device__ float g_x1[MROWS*C];
__device__ float g_t2[MROWS*C2];
__device__ float g_psum[131072];
__device__ float g_psq [131072];
__device__ float g_scale[C2];
__device__ float g_shift[C2];
__device__ float g_scale_pe[SSQ];
__device__ float g_shift_pe[SSQ];
// bf16 split buffers
__device__ __nv_bfloat16 g_ahi[MROWS*C2];
__device__ __nv_bfloat16 g_alo[MROWS*C2];
__device__ __nv_bfloat16 g_whi[C*C2];
__device__ __nv_bfloat16 g_wlo[C*C2];

// ---------------- BN stats: deterministic 2-stage reduction ----------------
__global__ void bn_partial(const float* __restrict__ X, int Cdim, int rowsPerBlock,
                           float* __restrict__ psum, float* __restrict__ psq) {
    int c = blockIdx.x * blockDim.x + threadIdx.x;
    int r0 = blockIdx.y * rowsPerBlock;
    float s = 0.f, q = 0.f;
    const float* Xp = X + (size_t)r0 * Cdim + c;
    for (int i = 0; i < rowsPerBlock; i++) {
        float v = Xp[(size_t)i * Cdim];
        s += v; q += v * v;
    }
    psum[(size_t)blockIdx.y * Cdim + c] = s;
    psq [(size_t)blockIdx.y * Cdim + c] = q;
}

__global__ void bn_finalize(const float* __restrict__ psum, const float* __restrict__ psq,
                            int Cdim, int nparts, float invM,
                            const float* __restrict__ g, const float* __restrict__ b,
                            float* __restrict__ scale, float* __restrict__ shift) {
    int c = blockIdx.x * blockDim.x + threadIdx.x;
    float s = 0.f, q = 0.f;
    for (int p = 0; p < nparts; p++) {
        s += psum[(size_t)p * Cdim + c];
        q += psq [(size_t)p * Cdim + c];
    }
    float mean = s * invM;
    float var  = q * invM - mean * mean;
    float sc   = g[c] * rsqrtf(var + 1e-5f);
    scale[c] = sc;
    shift[c] = b[c] - mean * sc;
}

// ---------------- fp32 -> bf16 hi/lo split (BN affine + relu fused) ---------
template<bool AFFINE, bool RELU>
__global__ void split_convert(const float* __restrict__ X,
                              const float* __restrict__ scale,
                              const float* __restrict__ shift,
                              __nv_bfloat16* __restrict__ hi,
                              __nv_bfloat16* __restrict__ lo,
                              int Kmask) {
    size_t i = (size_t)blockIdx.x * blockDim.x + threadIdx.x;
    float4 v = ((const float4*)X)[i];
    if (AFFINE) {
        int cb = (int)((i * 4) & Kmask);
        v.x = v.x * scale[cb+0] + shift[cb+0];
        v.y = v.y * scale[cb+1] + shift[cb+1];
        v.z = v.z * scale[cb+2] + shift[cb+2];
        v.w = v.w * scale[cb+3] + shift[cb+3];
    }
    if (RELU) {
        v.x = fmaxf(v.x, 0.f); v.y = fmaxf(v.y, 0.f);
        v.z = fmaxf(v.z, 0.f); v.w = fmaxf(v.w, 0.f);
    }
    __nv_bfloat16 h0 = __float2bfloat16(v.x), h1 = __float2bfloat16(v.y);
    __nv_bfloat16 h2 = __float2bfloat16(v.z), h3 = __float2bfloat16(v.w);
    __nv_bfloat16 l0 = __float2bfloat16(v.x - __bfloat162float(h0));
    __nv_bfloat16 l1 = __float2bfloat16(v.y - __bfloat162float(h1));
    __nv_bfloat16 l2 = __float2bfloat16(v.z - __bfloat162float(h2));
    __nv_bfloat16 l3 = __float2bfloat16(v.w - __bfloat162float(h3));
    ((__nv_bfloat162*)hi)[i*2]   = __nv_bfloat162(h0, h1);
    ((__nv_bfloat162*)hi)[i*2+1] = __nv_bfloat162(h2, h3);
    ((__nv_bfloat162*)lo)[i*2]   = __nv_bfloat162(l0, l1);
    ((__nv_bfloat162*)lo)[i*2+1] = __nv_bfloat162(l2, l3);
}

// ---------------- mma.sync helpers ----------------
__device__ __forceinline__ uint32_t smem_u32(const void* p) {
    uint32_t a;
    asm("{ .reg .u64 t; cvta.to.shared.u64 t, %1; cvt.u32.u64 %0, t; }" : "=r"(a) : "l"(p));
    return a;
}
__device__ __forceinline__ void ldm_x4(uint32_t* r, uint32_t addr) {
    asm volatile("ldmatrix.sync.aligned.m8n8.x4.shared.b16 {%0,%1,%2,%3}, [%4];"
                 : "=r"(r[0]), "=r"(r[1]), "=r"(r[2]), "=r"(r[3]) : "r"(addr));
}
__device__ __forceinline__ void ldm_x2(uint32_t* r, uint32_t addr) {
    asm volatile("ldmatrix.sync.aligned.m8n8.x2.shared.b16 {%0,%1}, [%2];"
                 : "=r"(r[0]), "=r"(r[1]) : "r"(addr));
}
__device__ __forceinline__ void mma_bf16(float* c, const uint32_t* a, const uint32_t* b) {
    asm volatile(
        "mma.sync.aligned.m16n8k16.row.col.f32.bf16.bf16.f32 "
        "{%0,%1,%2,%3}, {%4,%5,%6,%7}, {%8,%9}, {%0,%1,%2,%3};"
        : "+f"(c[0]), "+f"(c[1]), "+f"(c[2]), "+f"(c[3])
        : "r"(a[0]), "r"(a[1]), "r"(a[2]), "r"(a[3]), "r"(b[0]), "r"(b[1]));
}

// ---------------- split-bf16 GEMM via mma.sync ------------------------------
// Cout[M,N] = (Ah+Al)[M,K] @ (Bh+Bl)[N,K]^T  (+ bias, + residual)
// block tile 128x128, 8 warps (2M x 4N), warp tile 64x32, K-chunk 32,
// double-buffered SMEM with register staging.
// SMEM per stage: Ahi/Alo/Bhi/Blo, each 128 rows x 80B (32 bf16 + 16B pad).
#define STAGE_BYTES 40960
#define TILE_BYTES  10240
#define MMA_SMEM    (2*STAGE_BYTES)

template<bool BIAS, bool RES>
__global__ void __launch_bounds__(256, 1)
mma_gemm(const __nv_bfloat16* __restrict__ a_hi, const __nv_bfloat16* __restrict__ a_lo,
         const __nv_bfloat16* __restrict__ b_hi, const __nv_bfloat16* __restrict__ b_lo,
         float* __restrict__ Cout,
         const float* __restrict__ bias, const float* __restrict__ res,
         int M_, int N_, int K_) {
    extern __shared__ __align__(16) char sb[];
    const uint32_t sb32 = smem_u32(sb);

    const int t = threadIdx.x;
    const int lane = t & 31, warp = t >> 5;
    const int wm = warp & 1, wn = warp >> 1;     // 2 x 4 warp grid
    const int row0 = blockIdx.y * 128, col0 = blockIdx.x * 128;

    float acc[4][4][4];
    #pragma unroll
    for (int mi = 0; mi < 4; mi++)
        #pragma unroll
        for (int ni = 0; ni < 4; ni++)
            #pragma unroll
            for (int x = 0; x < 4; x++) acc[mi][ni][x] = 0.f;

    uint4 rah[2], ral[2], rbh[2], rbl[2];

    auto load_regs = [&](int k0) {
        #pragma unroll
        for (int i = 0; i < 2; i++) {
            int idx = t + i * 256;              // 0..511
            int r = idx >> 2, qq = idx & 3;
            size_t ga = (size_t)(row0 + r) * K_ + k0 + qq * 8;
            size_t gb = (size_t)(col0 + r) * K_ + k0 + qq * 8;
            rah[i] = *(const uint4*)(a_hi + ga);
            ral[i] = *(const uint4*)(a_lo + ga);
            rbh[i] = *(const uint4*)(b_hi + gb);
            rbl[i] = *(const uint4*)(b_lo + gb);
        }
    };
    auto store_smem = [&](int s) {
        char* base = sb + s * STAGE_BYTES;
        #pragma unroll
        for (int i = 0; i < 2; i++) {
            int idx = t + i * 256;
            int r = idx >> 2, qq = idx & 3;
            int off = r * 80 + qq * 16;
            *(uint4*)(base + off)                 = rah[i];
            *(uint4*)(base + TILE_BYTES   + off)  = ral[i];
            *(uint4*)(base + 2*TILE_BYTES + off)  = rbh[i];
            *(uint4*)(base + 3*TILE_BYTES + off)  = rbl[i];
        }
    };
    auto compute = [&](int s) {
        uint32_t base = sb32 + s * STAGE_BYTES;
        #pragma unroll
        for (int kk = 0; kk < 2; kk++) {
            uint32_t ah[4][4], al[4][4];
            #pragma unroll
            for (int mi = 0; mi < 4; mi++) {
                int r = wm * 64 + mi * 16 + (lane & 15);
                int cbyte = (kk * 16 + ((lane >> 4) << 3)) * 2;
                uint32_t addr = base + r * 80 + cbyte;
                ldm_x4(ah[mi], addr);
                ldm_x4(al[mi], addr + TILE_BYTES);
            }
            uint32_t bh[4][2], bl[4][2];
            #pragma unroll
            for (int ni = 0; ni < 4; ni++) {
                int r = wn * 32 + ni * 8 + (lane & 7);
                int cbyte = (kk * 16 + ((lane >> 3) & 1) * 8) * 2;
                uint32_t addr = base + 2*TILE_BYTES + r * 80 + cbyte;
                ldm_x2(bh[ni], addr);
                ldm_x2(bl[ni], addr + TILE_BYTES);
            }
            #pragma unroll
            for (int mi = 0; mi < 4; mi++)
                #pragma unroll
                for (int ni = 0; ni < 4; ni++) {
                    mma_bf16(acc[mi][ni], ah[mi], bh[ni]);
                    mma_bf16(acc[mi][ni], ah[mi], bl[ni]);
                    mma_bf16(acc[mi][ni], al[mi], bh[ni]);
                }
        }
    };

    load_regs(0);
    store_smem(0);
    __syncthreads();

    const int nchunk = K_ >> 5;
    for (int ch = 0; ch < nchunk; ch++) {
        int buf = ch & 1;
        if (ch + 1 < nchunk) load_regs((ch + 1) * 32);
        compute(buf);
        if (ch + 1 < nchunk) store_smem(buf ^ 1);
        __syncthreads();
    }

    // epilogue: c-frag thread t holds rows (t/4, t/4+8), cols 2*(t%4)..+1
    const int tr = lane >> 2, tc = (lane & 3) * 2;
    #pragma unroll
    for (int mi = 0; mi < 4; mi++) {
        #pragma unroll
        for (int ni = 0; ni < 4; ni++) {
            int rr = row0 + wm * 64 + mi * 16 + tr;
            int cc = col0 + wn * 32 + ni * 8 + tc;
            float v0 = acc[mi][ni][0], v1 = acc[mi][ni][1];
            float v2 = acc[mi][ni][2], v3 = acc[mi][ni][3];
            if (BIAS) { v0 += bias[cc]; v1 += bias[cc+1]; v2 += bias[cc]; v3 += bias[cc+1]; }
            if (RES) {
                const float2 r0v = *(const float2*)&res[(size_t)rr * N_ + cc];
                const float2 r1v = *(const float2*)&res[(size_t)(rr+8) * N_ + cc];
                v0 += r0v.x; v1 += r0v.y; v2 += r1v.x; v3 += r1v.y;
            }
            *(float2*)&Cout[(size_t)rr * N_ + cc]       = make_float2(v0, v1);
            *(float2*)&Cout[(size_t)(rr+8) * N_ + cc]   = make_float2(v2, v3);
        }
    }
}

// ---------------- energy[n,h,q,k] = sum_d q*k (fp32 SIMT, FFMA2) ------------
typedef unsigned long long u64;
__device__ __forceinline__ u64 pack2(float x) {
    u64 r; unsigned u = __float_as_uint(x);
    asm("mov.b64 %0, {%1, %1};" : "=l"(r) : "r"(u));
    return r;
}
__device__ __forceinline__ void ffma2(u64& d, u64 a, u64 b) {
    asm("fma.rn.f32x2 %0, %1, %2, %0;" : "+l"(d) : "l"(a), "l"(b));
}
__device__ __forceinline__ float lo32(u64 v) { return __uint_as_float((unsigned)v); }
__device__ __forceinline__ float hi32(u64 v) { return __uint_as_float((unsigned)(v >> 32)); }

__global__ void energy_kernel(const float* __restrict__ Q, const float* __restrict__ Kt,
                              float* __restrict__ E) {
    int nh = blockIdx.x;
    int n = nh >> 3, h = nh & 7;
    __shared__ __align__(16) float qs[32][132];
    __shared__ __align__(16) float ks[32][132];
    int t = threadIdx.x;
    int dd = t & 31, sbw = t >> 5;
    const float* qb = Q + ((size_t)(n * S) * H + h) * D;
    const float* kb = Kt + ((size_t)(n * S) * H + h) * D;
    #pragma unroll
    for (int p = 0; p < 16; p++) {
        int s = p * 8 + sbw;
        qs[dd][s] = qb[(size_t)s * (H * D) + dd];
        ks[dd][s] = kb[(size_t)s * (H * D) + dd];
    }
    __syncthreads();
    int ty = t >> 4, tx = t & 15;
    u64 acc[8][4];
    #pragma unroll
    for (int i = 0; i < 8; i++)
        #pragma unroll
        for (int j = 0; j < 4; j++) acc[i][j] = 0ull;
    #pragma unroll
    for (int k = 0; k < 32; k++) {
        float4 a0 = *(const float4*)&qs[k][ty * 8];
        float4 a1 = *(const float4*)&qs[k][ty * 8 + 4];
        ulonglong2 b0 = *(const ulonglong2*)&ks[k][tx * 8];
        ulonglong2 b1 = *(const ulonglong2*)&ks[k][tx * 8 + 4];
        u64 bb[4] = {b0.x, b0.y, b1.x, b1.y};
        float a[8] = {a0.x, a0.y, a0.z, a0.w, a1.x, a1.y, a1.z, a1.w};
        #pragma unroll
        for (int i = 0; i < 8; i++) {
            u64 ad = pack2(a[i]);
            #pragma unroll
            for (int j = 0; j < 4; j++) ffma2(acc[i][j], ad, bb[j]);
        }
    }
    float* eb = E + (size_t)nh * SSQ;
    #pragma unroll
    for (int i = 0; i < 8; i++) {
        float vout[8];
        #pragma unroll
        for (int j = 0; j < 4; j++) { vout[2*j] = lo32(acc[i][j]); vout[2*j+1] = hi32(acc[i][j]); }
        *(float4*)&eb[(size_t)(ty * 8 + i) * S + tx * 8]     = make_float4(vout[0], vout[1], vout[2], vout[3]);
        *(float4*)&eb[(size_t)(ty * 8 + i) * S + tx * 8 + 4] = make_float4(vout[4], vout[5], vout[6], vout[7]);
    }
}

// ---------------- fused BN(affine) + /sqrt(C) + softmax ---------------------
__global__ void softmax_kernel(float* __restrict__ E,
                               const float* __restrict__ scale,
                               const float* __restrict__ shift) {
    int warp = threadIdx.x >> 5, lane = threadIdx.x & 31;
    int row = blockIdx.x * 8 + warp;
    int qi = row & (S - 1);
    float* e = E + (size_t)row * S;
    const float* sc = scale + qi * S;
    const float* sh = shift + qi * S;
    float v[4];
    float mx = -INFINITY;
    #pragma unroll
    for (int i = 0; i < 4; i++) {
        int ki = i * 32 + lane;
        v[i] = (e[ki] * sc[ki] + sh[ki]) * 0.0625f;
        mx = fmaxf(mx, v[i]);
    }
    #pragma unroll
    for (int off = 16; off > 0; off >>= 1)
        mx = fmaxf(mx, __shfl_xor_sync(0xffffffffu, mx, off));
    float sum = 0.f;
    #pragma unroll
    for (int i = 0; i < 4; i++) { v[i] = __expf(v[i] - mx); sum += v[i]; }
    #pragma unroll
    for (int off = 16; off > 0; off >>= 1)
        sum += __shfl_xor_sync(0xffffffffu, sum, off);
    float inv = 1.f / sum;
    #pragma unroll
    for (int i = 0; i < 4; i++)
        e[i * 32 + lane] = v[i] * inv;
}

// ---------------- o[n,q,h,d] = sum_l attn[n,h,q,l] * v[n,l,h,d] -------------
__global__ void av_kernel(const float* __restrict__ A, const float* __restrict__ V,
                          float* __restrict__ O) {
    int nh = blockIdx.x;
    int n = nh >> 3, h = nh & 7;
    __shared__ float as_[128][33];
    __shared__ float vs[32][33];
    int t = threadIdx.x;
    const float* ab = A + (size_t)nh * SSQ;
    const float* vb = V + ((size_t)(n * S) * H + h) * D;
    int col = t & 31, rb = t >> 5;
    int ty = t >> 3, tx = t & 7;
    float acc[4][4] = {};
    for (int lc = 0; lc < 4; lc++) {
        int l0 = lc * 32;
        #pragma unroll
        for (int p = 0; p < 16; p++) {
            int r = p * 8 + rb;
            as_[r][col] = ab[(size_t)r * S + l0 + col];
        }
        #pragma unroll
        for (int p = 0; p < 4; p++) {
            int r = p * 8 + rb;
            vs[r][col] = vb[(size_t)(l0 + r) * (H * D) + col];
        }
        __syncthreads();
        #pragma unroll
        for (int l = 0; l < 32; l++) {
            float a[4], b[4];
            #pragma unroll
            for (int i = 0; i < 4; i++) a[i] = as_[ty * 4 + i][l];
            #pragma unroll
            for (int j = 0; j < 4; j++) b[j] = vs[l][tx * 4 + j];
            #pragma unroll
            for (int i = 0; i < 4; i++)
                #pragma unroll
                for (int j = 0; j < 4; j++)
                    acc[i][j] += a[i] * b[j];
        }
        __syncthreads();
    }
    float* ob = O + ((size_t)(n * S) * H + h) * D;
    #pragma unroll
    for (int i = 0; i < 4; i++)
        #pragma unroll
        for (int j = 0; j < 4; j++)
            ob[(size_t)(ty * 4 + i) * (H * D) + tx * 4 + j] = acc[i][j];
}

// ---------------------------------------------------------------------------
extern "C" void kernel_launch(void* const* d_in, const int* in_sizes, int n_in,
                              void* d_out, int out_size) {
    const float* x    = (const float*)d_in[0];
    const float* g_n  = (const float*)d_in[1];
    const float* b_n  = (const float*)d_in[2];
    const float* Wq   = (const float*)d_in[3];
    const float* Wk   = (const float*)d_in[4];
    const float* Wv   = (const float*)d_in[5];
    const float* Wo   = (const float*)d_in[6];
    const float* bo   = (const float*)d_in[7];
    const float* g_pe = (const float*)d_in[8];
    const float* b_pe = (const float*)d_in[9];
    const float* g0   = (const float*)d_in[10];
    const float* b0   = (const float*)d_in[11];
    const float* W0   = (const float*)d_in[12];
    const float* g1   = (const float*)d_in[13];
    const float* b1   = (const float*)d_in[14];
    const float* W1   = (const float*)d_in[15];
    float* out = (float*)d_out;

    float *q, *k, *v, *e, *o, *x1, *t2, *psum, *psq, *sc, *sh, *scpe, *shpe;
    __nv_bfloat16 *ahi, *alo, *whi, *wlo;
    cudaGetSymbolAddress((void**)&q,    g_q);
    cudaGetSymbolAddress((void**)&k,    g_k);
    cudaGetSymbolAddress((void**)&v,    g_v);
    cudaGetSymbolAddress((void**)&e,    g_e);
    cudaGetSymbolAddress((void**)&o,    g_o);
    cudaGetSymbolAddress((void**)&x1,   g_x1);
    cudaGetSymbolAddress((void**)&t2,   g_t2);
    cudaGetSymbolAddress((void**)&psum, g_psum);
    cudaGetSymbolAddress((void**)&psq,  g_psq);
    cudaGetSymbolAddress((void**)&sc,   g_scale);
    cudaGetSymbolAddress((void**)&sh,   g_shift);
    cudaGetSymbolAddress((void**)&scpe, g_scale_pe);
    cudaGetSymbolAddress((void**)&shpe, g_shift_pe);
    cudaGetSymbolAddress((void**)&ahi,  g_ahi);
    cudaGetSymbolAddress((void**)&alo,  g_alo);
    cudaGetSymbolAddress((void**)&whi,  g_whi);
    cudaGetSymbolAddress((void**)&wlo,  g_wlo);

    cudaFuncSetAttribute(mma_gemm<false,false>, cudaFuncAttributeMaxDynamicSharedMemorySize, MMA_SMEM);
    cudaFuncSetAttribute(mma_gemm<true, true >, cudaFuncAttributeMaxDynamicSharedMemorySize, MMA_SMEM);
    cudaFuncSetAttribute(mma_gemm<false,true >, cudaFuncAttributeMaxDynamicSharedMemorySize, MMA_SMEM);

    // --- BN over C on x -> scale/shift ---
    bn_partial<<<dim3(1, 128), 256>>>(x, C, 256, psum, psq);
    bn_finalize<<<1, 256>>>(psum, psq, C, 128, 1.f / MROWS, g_n, b_n, sc, sh);

    // --- convert bn(x) to bf16 split ---
    split_convert<true, false><<<MROWS * C / 1024, 256>>>(x, sc, sh, ahi, alo, C - 1);

    // --- q/k/v ---
    dim3 gqkv(C / 128, MROWS / 128);
    split_convert<false, false><<<C * C / 1024, 256>>>(Wq, nullptr, nullptr, whi, wlo, 3);
    mma_gemm<false,false><<<gqkv, 256, MMA_SMEM>>>(ahi, alo, whi, wlo, q, nullptr, nullptr, MROWS, C, C);
    split_convert<false, false><<<C * C / 1024, 256>>>(Wk, nullptr, nullptr, whi, wlo, 3);
    mma_gemm<false,false><<<gqkv, 256, MMA_SMEM>>>(ahi, alo, whi, wlo, k, nullptr, nullptr, MROWS, C, C);
    split_convert<false, false><<<C * C / 1024, 256>>>(Wv, nullptr, nullptr, whi, wlo, 3);
    mma_gemm<false,false><<<gqkv, 256, MMA_SMEM>>>(ahi, alo, whi, wlo, v, nullptr, nullptr, MROWS, C, C);

    // --- energy ---
    energy_kernel<<<NHB, 256>>>(q, k, e);

    // --- BN over S*S positions on energy ---
    bn_partial<<<dim3(SSQ / 256, 8), 256>>>(e, SSQ, 256, psum, psq);
    bn_finalize<<<SSQ / 256, 256>>>(psum, psq, SSQ, 8, 1.f / NHB, g_pe, b_pe, scpe, shpe);

    // --- fused BN + scale + softmax ---
    softmax_kernel<<<(NHB * S) / 8, 256>>>(e, scpe, shpe);

    // --- o = attn @ v ---
    av_kernel<<<NHB, 256>>>(e, v, o);

    // --- x1 = o @ Wo^T + bo + x ---
    split_convert<false, false><<<MROWS * C / 1024, 256>>>(o, nullptr, nullptr, ahi, alo, C - 1);
    split_convert<false, false><<<C * C / 1024, 256>>>(Wo, nullptr, nullptr, whi, wlo, 3);
    mma_gemm<true, true><<<gqkv, 256, MMA_SMEM>>>(ahi, alo, whi, wlo, x1, bo, x, MROWS, C, C);

    // --- FFN: BN0 -> relu -> W0 ---
    bn_partial<<<dim3(1, 128), 256>>>(x1, C, 256, psum, psq);
    bn_finalize<<<1, 256>>>(psum, psq, C, 128, 1.f / MROWS, g0, b0, sc, sh);
    split_convert<true, true><<<MROWS * C / 1024, 256>>>(x1, sc, sh, ahi, alo, C - 1);
    split_convert<false, false><<<C2 * C / 1024, 256>>>(W0, nullptr, nullptr, whi, wlo, 3);
    dim3 gffn0(C2 / 128, MROWS / 128);
    mma_gemm<false,false><<<gffn0, 256, MMA_SMEM>>>(ahi, alo, whi, wlo, t2, nullptr, nullptr, MROWS, C2, C);

    // --- BN1 -> relu -> W1 -> + x1 ---
    bn_partial<<<dim3(2, 128), 256>>>(t2, C2, 256, psum, psq);
    bn_finalize<<<2, 256>>>(psum, psq, C2, 128, 1.f / MROWS, g1, b1, sc, sh);
    split_convert<true, true><<<MROWS * C2 / 1024, 256>>>(t2, sc, sh, ahi, alo, C2 - 1);
    split_convert<false, false><<<C * C2 / 1024, 256>>>(W1, nullptr, nullptr, whi, wlo, 3);
    mma_gemm<false, true><<<gqkv, 256, MMA_SMEM>>>(ahi, alo, whi, wlo, out, nullptr, x1, MROWS, C, C2);
}

// round 5
// speedup vs baseline: 1.9041x; 1.0030x over previous
#include <cuda_runtime.h>
#include <cuda_bf16.h>
#include <math.h>
#include <stdint.h>

// Problem constants
#define MB  256
#define S   128
#define C   256
#define H   8
#define D   32
#define MROWS (MB*S)           // 32768
#define C2  (2*C)              // 512
#define NHB (MB*H)             // 2048
#define SSQ (S*S)              // 16384

// ---------------- scratch (device globals) ----------------
__device__ float g_v [MROWS*C];
__device__ float g_e [NHB*SSQ];
__device__ float g_x1[MROWS*C];
__device__ float g_t2[MROWS*C2];
__device__ float g_psum[131072];
__device__ float g_psq [131072];
__device__ float g_scale[C2];
__device__ float g_shift[C2];
__device__ float g_scale_pe[SSQ];
__device__ float g_shift_pe[SSQ];
// bf16 split buffers
__device__ __nv_bfloat16 g_ahi[MROWS*C2];
__device__ __nv_bfloat16 g_alo[MROWS*C2];
__device__ __nv_bfloat16 g_whi[C*C2];
__device__ __nv_bfloat16 g_wlo[C*C2];
__device__ __nv_bfloat16 g_qhi[MROWS*C];
__device__ __nv_bfloat16 g_qlo[MROWS*C];
__device__ __nv_bfloat16 g_khi[MROWS*C];
__device__ __nv_bfloat16 g_klo[MROWS*C];
__device__ __nv_bfloat16 g_ohi[MROWS*C];
__device__ __nv_bfloat16 g_olo[MROWS*C];

// ---------------- BN stats: deterministic 2-stage reduction ----------------
__global__ void bn_partial(const float* __restrict__ X, int Cdim, int rowsPerBlock,
                           float* __restrict__ psum, float* __restrict__ psq) {
    int c = blockIdx.x * blockDim.x + threadIdx.x;
    int r0 = blockIdx.y * rowsPerBlock;
    float s = 0.f, q = 0.f;
    const float* Xp = X + (size_t)r0 * Cdim + c;
    for (int i = 0; i < rowsPerBlock; i++) {
        float v = Xp[(size_t)i * Cdim];
        s += v; q += v * v;
    }
    psum[(size_t)blockIdx.y * Cdim + c] = s;
    psq [(size_t)blockIdx.y * Cdim + c] = q;
}

__global__ void bn_finalize(const float* __restrict__ psum, const float* __restrict__ psq,
                            int Cdim, int nparts, float invM,
                            const float* __restrict__ g, const float* __restrict__ b,
                            float* __restrict__ scale, float* __restrict__ shift) {
    int c = blockIdx.x * blockDim.x + threadIdx.x;
    float s = 0.f, q = 0.f;
    for (int p = 0; p < nparts; p++) {
        s += psum[(size_t)p * Cdim + c];
        q += psq [(size_t)p * Cdim + c];
    }
    float mean = s * invM;
    float var  = q * invM - mean * mean;
    float sc   = g[c] * rsqrtf(var + 1e-5f);
    scale[c] = sc;
    shift[c] = b[c] - mean * sc;
}

// ---------------- fp32 -> bf16 hi/lo split (BN affine + relu fused) ---------
template<bool AFFINE, bool RELU>
__global__ void split_convert(const float* __restrict__ X,
                              const float* __restrict__ scale,
                              const float* __restrict__ shift,
                              __nv_bfloat16* __restrict__ hi,
                              __nv_bfloat16* __restrict__ lo,
                              int Kmask) {
    size_t i = (size_t)blockIdx.x * blockDim.x + threadIdx.x;
    float4 v = ((const float4*)X)[i];
    if (AFFINE) {
        int cb = (int)((i * 4) & Kmask);
        v.x = v.x * scale[cb+0] + shift[cb+0];
        v.y = v.y * scale[cb+1] + shift[cb+1];
        v.z = v.z * scale[cb+2] + shift[cb+2];
        v.w = v.w * scale[cb+3] + shift[cb+3];
    }
    if (RELU) {
        v.x = fmaxf(v.x, 0.f); v.y = fmaxf(v.y, 0.f);
        v.z = fmaxf(v.z, 0.f); v.w = fmaxf(v.w, 0.f);
    }
    __nv_bfloat16 h0 = __float2bfloat16(v.x), h1 = __float2bfloat16(v.y);
    __nv_bfloat16 h2 = __float2bfloat16(v.z), h3 = __float2bfloat16(v.w);
    __nv_bfloat16 l0 = __float2bfloat16(v.x - __bfloat162float(h0));
    __nv_bfloat16 l1 = __float2bfloat16(v.y - __bfloat162float(h1));
    __nv_bfloat16 l2 = __float2bfloat16(v.z - __bfloat162float(h2));
    __nv_bfloat16 l3 = __float2bfloat16(v.w - __bfloat162float(h3));
    ((__nv_bfloat162*)hi)[i*2]   = __nv_bfloat162(h0, h1);
    ((__nv_bfloat162*)hi)[i*2+1] = __nv_bfloat162(h2, h3);
    ((__nv_bfloat162*)lo)[i*2]   = __nv_bfloat162(l0, l1);
    ((__nv_bfloat162*)lo)[i*2+1] = __nv_bfloat162(l2, l3);
}

// ---------------- mma.sync helpers ----------------
__device__ __forceinline__ uint32_t smem_u32(const void* p) {
    uint32_t a;
    asm("{ .reg .u64 t; cvta.to.shared.u64 t, %1; cvt.u32.u64 %0, t; }" : "=r"(a) : "l"(p));
    return a;
}
__device__ __forceinline__ void ldm_x4(uint32_t* r, uint32_t addr) {
    asm volatile("ldmatrix.sync.aligned.m8n8.x4.shared.b16 {%0,%1,%2,%3}, [%4];"
                 : "=r"(r[0]), "=r"(r[1]), "=r"(r[2]), "=r"(r[3]) : "r"(addr));
}
__device__ __forceinline__ void ldm_x2(uint32_t* r, uint32_t addr) {
    asm volatile("ldmatrix.sync.aligned.m8n8.x2.shared.b16 {%0,%1}, [%2];"
                 : "=r"(r[0]), "=r"(r[1]) : "r"(addr));
}
__device__ __forceinline__ void mma_bf16(float* c, const uint32_t* a, const uint32_t* b) {
    asm volatile(
        "mma.sync.aligned.m16n8k16.row.col.f32.bf16.bf16.f32 "
        "{%0,%1,%2,%3}, {%4,%5,%6,%7}, {%8,%9}, {%0,%1,%2,%3};"
        : "+f"(c[0]), "+f"(c[1]), "+f"(c[2]), "+f"(c[3])
        : "r"(a[0]), "r"(a[1]), "r"(a[2]), "r"(a[3]), "r"(b[0]), "r"(b[1]));
}

// ---------------- split-bf16 GEMM via mma.sync ------------------------------
// block tile 128x128, 8 warps (2M x 4N), warp tile 64x32, K-chunk 32,
// double-buffered SMEM with register staging.
#define STAGE_BYTES 40960
#define TILE_BYTES  10240
#define MMA_SMEM    (2*STAGE_BYTES)

template<bool BIAS, bool RES, bool SPLITOUT>
__global__ void __launch_bounds__(256, 1)
mma_gemm(const __nv_bfloat16* __restrict__ a_hi, const __nv_bfloat16* __restrict__ a_lo,
         const __nv_bfloat16* __restrict__ b_hi, const __nv_bfloat16* __restrict__ b_lo,
         float* __restrict__ Cout,
         __nv_bfloat16* __restrict__ out_hi, __nv_bfloat16* __restrict__ out_lo,
         const float* __restrict__ bias, const float* __restrict__ res,
         int M_, int N_, int K_) {
    extern __shared__ __align__(16) char sb[];
    const uint32_t sb32 = smem_u32(sb);

    const int t = threadIdx.x;
    const int lane = t & 31, warp = t >> 5;
    const int wm = warp & 1, wn = warp >> 1;
    const int row0 = blockIdx.y * 128, col0 = blockIdx.x * 128;

    float acc[4][4][4];
    #pragma unroll
    for (int mi = 0; mi < 4; mi++)
        #pragma unroll
        for (int ni = 0; ni < 4; ni++)
            #pragma unroll
            for (int x = 0; x < 4; x++) acc[mi][ni][x] = 0.f;

    uint4 rah[2], ral[2], rbh[2], rbl[2];

    auto load_regs = [&](int k0) {
        #pragma unroll
        for (int i = 0; i < 2; i++) {
            int idx = t + i * 256;
            int r = idx >> 2, qq = idx & 3;
            size_t ga = (size_t)(row0 + r) * K_ + k0 + qq * 8;
            size_t gb = (size_t)(col0 + r) * K_ + k0 + qq * 8;
            rah[i] = *(const uint4*)(a_hi + ga);
            ral[i] = *(const uint4*)(a_lo + ga);
            rbh[i] = *(const uint4*)(b_hi + gb);
            rbl[i] = *(const uint4*)(b_lo + gb);
        }
    };
    auto store_smem = [&](int s) {
        char* base = sb + s * STAGE_BYTES;
        #pragma unroll
        for (int i = 0; i < 2; i++) {
            int idx = t + i * 256;
            int r = idx >> 2, qq = idx & 3;
            int off = r * 80 + qq * 16;
            *(uint4*)(base + off)                 = rah[i];
            *(uint4*)(base + TILE_BYTES   + off)  = ral[i];
            *(uint4*)(base + 2*TILE_BYTES + off)  = rbh[i];
            *(uint4*)(base + 3*TILE_BYTES + off)  = rbl[i];
        }
    };
    auto compute = [&](int s) {
        uint32_t base = sb32 + s * STAGE_BYTES;
        #pragma unroll
        for (int kk = 0; kk < 2; kk++) {
            uint32_t ah[4][4], al[4][4];
            #pragma unroll
            for (int mi = 0; mi < 4; mi++) {
                int r = wm * 64 + mi * 16 + (lane & 15);
                int cbyte = (kk * 16 + ((lane >> 4) << 3)) * 2;
                uint32_t addr = base + r * 80 + cbyte;
                ldm_x4(ah[mi], addr);
                ldm_x4(al[mi], addr + TILE_BYTES);
            }
            uint32_t bh[4][2], bl[4][2];
            #pragma unroll
            for (int ni = 0; ni < 4; ni++) {
                int r = wn * 32 + ni * 8 + (lane & 7);
                int cbyte = (kk * 16 + ((lane >> 3) & 1) * 8) * 2;
                uint32_t addr = base + 2*TILE_BYTES + r * 80 + cbyte;
                ldm_x2(bh[ni], addr);
                ldm_x2(bl[ni], addr + TILE_BYTES);
            }
            #pragma unroll
            for (int mi = 0; mi < 4; mi++)
                #pragma unroll
                for (int ni = 0; ni < 4; ni++) {
                    mma_bf16(acc[mi][ni], ah[mi], bh[ni]);
                    mma_bf16(acc[mi][ni], ah[mi], bl[ni]);
                    mma_bf16(acc[mi][ni], al[mi], bh[ni]);
                }
        }
    };

    load_regs(0);
    store_smem(0);
    __syncthreads();

    const int nchunk = K_ >> 5;
    for (int ch = 0; ch < nchunk; ch++) {
        int buf = ch & 1;
        if (ch + 1 < nchunk) load_regs((ch + 1) * 32);
        compute(buf);
        if (ch + 1 < nchunk) store_smem(buf ^ 1);
        __syncthreads();
    }

    const int tr = lane >> 2, tc = (lane & 3) * 2;
    #pragma unroll
    for (int mi = 0; mi < 4; mi++) {
        #pragma unroll
        for (int ni = 0; ni < 4; ni++) {
            int rr = row0 + wm * 64 + mi * 16 + tr;
            int cc = col0 + wn * 32 + ni * 8 + tc;
            float v0 = acc[mi][ni][0], v1 = acc[mi][ni][1];
            float v2 = acc[mi][ni][2], v3 = acc[mi][ni][3];
            if (BIAS) { v0 += bias[cc]; v1 += bias[cc+1]; v2 += bias[cc]; v3 += bias[cc+1]; }
            if (RES) {
                const float2 r0v = *(const float2*)&res[(size_t)rr * N_ + cc];
                const float2 r1v = *(const float2*)&res[(size_t)(rr+8) * N_ + cc];
                v0 += r0v.x; v1 += r0v.y; v2 += r1v.x; v3 += r1v.y;
            }
            if (SPLITOUT) {
                __nv_bfloat16 h0 = __float2bfloat16(v0), h1 = __float2bfloat16(v1);
                __nv_bfloat16 h2 = __float2bfloat16(v2), h3 = __float2bfloat16(v3);
                __nv_bfloat16 l0 = __float2bfloat16(v0 - __bfloat162float(h0));
                __nv_bfloat16 l1 = __float2bfloat16(v1 - __bfloat162float(h1));
                __nv_bfloat16 l2 = __float2bfloat16(v2 - __bfloat162float(h2));
                __nv_bfloat16 l3 = __float2bfloat16(v3 - __bfloat162float(h3));
                *(__nv_bfloat162*)(out_hi + (size_t)rr * N_ + cc)     = __nv_bfloat162(h0, h1);
                *(__nv_bfloat162*)(out_hi + (size_t)(rr+8) * N_ + cc) = __nv_bfloat162(h2, h3);
                *(__nv_bfloat162*)(out_lo + (size_t)rr * N_ + cc)     = __nv_bfloat162(l0, l1);
                *(__nv_bfloat162*)(out_lo + (size_t)(rr+8) * N_ + cc) = __nv_bfloat162(l2, l3);
            } else {
                *(float2*)&Cout[(size_t)rr * N_ + cc]     = make_float2(v0, v1);
                *(float2*)&Cout[(size_t)(rr+8) * N_ + cc] = make_float2(v2, v3);
            }
        }
    }
}

// ---------------- energy via mma.sync: e[nh] = q_tile @ k_tile^T ------------
// per (n,h): A = q [128 x 32] hi/lo, B = k [128 x 32] hi/lo. One K-chunk of 32.
__global__ void __launch_bounds__(256, 2)
energy_mma(const __nv_bfloat16* __restrict__ qhi, const __nv_bfloat16* __restrict__ qlo,
           const __nv_bfloat16* __restrict__ khi, const __nv_bfloat16* __restrict__ klo,
           float* __restrict__ E) {
    __shared__ __align__(16) char sb[4 * TILE_BYTES];
    const uint32_t sb32 = smem_u32(sb);
    const int nh = blockIdx.x;
    const int n = nh >> 3, h = nh & 7;
    const int t = threadIdx.x;
    const int lane = t & 31, warp = t >> 5;
    const int wm = warp & 1, wn = warp >> 1;

    const __nv_bfloat16* qh = qhi + ((size_t)(n * S) * H + h) * D;
    const __nv_bfloat16* ql = qlo + ((size_t)(n * S) * H + h) * D;
    const __nv_bfloat16* kh = khi + ((size_t)(n * S) * H + h) * D;
    const __nv_bfloat16* kl = klo + ((size_t)(n * S) * H + h) * D;

    // load 4 tiles of [128 rows x 32 bf16] into smem (row stride 80B)
    #pragma unroll
    for (int i = 0; i < 2; i++) {
        int idx = t + i * 256;          // 0..511 = 128 rows x 4 quads
        int r = idx >> 2, qq = idx & 3;
        size_t g = (size_t)r * (H * D) + qq * 8;
        int off = r * 80 + qq * 16;
        *(uint4*)(sb + off)                 = *(const uint4*)(qh + g);
        *(uint4*)(sb + TILE_BYTES   + off)  = *(const uint4*)(ql + g);
        *(uint4*)(sb + 2*TILE_BYTES + off)  = *(const uint4*)(kh + g);
        *(uint4*)(sb + 3*TILE_BYTES + off)  = *(const uint4*)(kl + g);
    }
    __syncthreads();

    float acc[4][4][4];
    #pragma unroll
    for (int mi = 0; mi < 4; mi++)
        #pragma unroll
        for (int ni = 0; ni < 4; ni++)
            #pragma unroll
            for (int x = 0; x < 4; x++) acc[mi][ni][x] = 0.f;

    #pragma unroll
    for (int kk = 0; kk < 2; kk++) {
        uint32_t ah[4][4], al[4][4];
        #pragma unroll
        for (int mi = 0; mi < 4; mi++) {
            int r = wm * 64 + mi * 16 + (lane & 15);
            int cbyte = (kk * 16 + ((lane >> 4) << 3)) * 2;
            uint32_t addr = sb32 + r * 80 + cbyte;
            ldm_x4(ah[mi], addr);
            ldm_x4(al[mi], addr + TILE_BYTES);
        }
        uint32_t bh[4][2], bl[4][2];
        #pragma unroll
        for (int ni = 0; ni < 4; ni++) {
            int r = wn * 32 + ni * 8 + (lane & 7);
            int cbyte = (kk * 16 + ((lane >> 3) & 1) * 8) * 2;
            uint32_t addr = sb32 + 2*TILE_BYTES + r * 80 + cbyte;
            ldm_x2(bh[ni], addr);
            ldm_x2(bl[ni], addr + TILE_BYTES);
        }
        #pragma unroll
        for (int mi = 0; mi < 4; mi++)
            #pragma unroll
            for (int ni = 0; ni < 4; ni++) {
                mma_bf16(acc[mi][ni], ah[mi], bh[ni]);
                mma_bf16(acc[mi][ni], ah[mi], bl[ni]);
                mma_bf16(acc[mi][ni], al[mi], bh[ni]);
            }
    }

    float* eb = E + (size_t)nh * SSQ;
    const int tr = lane >> 2, tc = (lane & 3) * 2;
    #pragma unroll
    for (int mi = 0; mi < 4; mi++)
        #pragma unroll
        for (int ni = 0; ni < 4; ni++) {
            int rr = wm * 64 + mi * 16 + tr;
            int cc = wn * 32 + ni * 8 + tc;
            *(float2*)&eb[(size_t)rr * S + cc]     = make_float2(acc[mi][ni][0], acc[mi][ni][1]);
            *(float2*)&eb[(size_t)(rr+8) * S + cc] = make_float2(acc[mi][ni][2], acc[mi][ni][3]);
        }
}

// ---------------- fused BN(affine) + softmax + AV, split-bf16 output --------
// per (n,h): softmax over e rows into smem attn[128][129], then o = attn @ v.
#define SAV_SMEM (128*129*4 + 128*36*4)   // 66048 + 18432 = 84480

typedef unsigned long long u64;
__device__ __forceinline__ u64 pack2(float x) {
    u64 r; unsigned u = __float_as_uint(x);
    asm("mov.b64 %0, {%1, %1};" : "=l"(r) : "r"(u));
    return r;
}
__device__ __forceinline__ void ffma2(u64& d, u64 a, u64 b) {
    asm("fma.rn.f32x2 %0, %1, %2, %0;" : "+l"(d) : "l"(a), "l"(b));
}
__device__ __forceinline__ float lo32(u64 v) { return __uint_as_float((unsigned)v); }
__device__ __forceinline__ float hi32(u64 v) { return __uint_as_float((unsigned)(v >> 32)); }

__global__ void __launch_bounds__(256, 2)
softmax_av(const float* __restrict__ E,
           const float* __restrict__ scpe, const float* __restrict__ shpe,
           const float* __restrict__ V,
           __nv_bfloat16* __restrict__ ohi, __nv_bfloat16* __restrict__ olo) {
    extern __shared__ __align__(16) float smf[];
    float* attn = smf;                  // [128][129]
    float* vs   = smf + 128 * 129;      // [128][36]
    const int nh = blockIdx.x;
    const int n = nh >> 3, h = nh & 7;
    const int t = threadIdx.x;
    const int lane = t & 31, warp = t >> 5;

    // load v tile [128 x 32] fp32
    const float* vb = V + ((size_t)(n * S) * H + h) * D;
    #pragma unroll
    for (int i = 0; i < 4; i++) {
        int idx = t + i * 256;          // 0..1023 = 128 rows x 8 quads
        int l = idx >> 3, qq = idx & 7;
        *(float4*)&vs[l * 36 + qq * 4] = *(const float4*)&vb[(size_t)l * (H * D) + qq * 4];
    }

    // softmax: each warp 16 rows
    const float* eb = E + (size_t)nh * SSQ;
    for (int rr = 0; rr < 16; rr++) {
        int row = warp * 16 + rr;
        const float* e = eb + (size_t)row * S;
        const float* sc = scpe + row * S;
        const float* sh = shpe + row * S;
        float v[4];
        float mx = -INFINITY;
        #pragma unroll
        for (int i = 0; i < 4; i++) {
            int ki = i * 32 + lane;
            v[i] = (e[ki] * sc[ki] + sh[ki]) * 0.0625f;
            mx = fmaxf(mx, v[i]);
        }
        #pragma unroll
        for (int off = 16; off > 0; off >>= 1)
            mx = fmaxf(mx, __shfl_xor_sync(0xffffffffu, mx, off));
        float sum = 0.f;
        #pragma unroll
        for (int i = 0; i < 4; i++) { v[i] = __expf(v[i] - mx); sum += v[i]; }
        #pragma unroll
        for (int off = 16; off > 0; off >>= 1)
            sum += __shfl_xor_sync(0xffffffffu, sum, off);
        float inv = 1.f / sum;
        #pragma unroll
        for (int i = 0; i < 4; i++)
            attn[row * 129 + i * 32 + lane] = v[i] * inv;
    }
    __syncthreads();

    // AV: o[128][32], each thread 4 rows x 4 cols, FFMA2 over col pairs
    const int ty = t >> 3, tx = t & 7;
    u64 acc[4][2];
    #pragma unroll
    for (int i = 0; i < 4; i++) { acc[i][0] = 0ull; acc[i][1] = 0ull; }
    for (int l = 0; l < 128; l++) {
        u64 b0 = *(const u64*)&vs[l * 36 + tx * 4];
        u64 b1 = *(const u64*)&vs[l * 36 + tx * 4 + 2];
        #pragma unroll
        for (int i = 0; i < 4; i++) {
            u64 ad = pack2(attn[(ty * 4 + i) * 129 + l]);
            ffma2(acc[i][0], ad, b0);
            ffma2(acc[i][1], ad, b1);
        }
    }
    #pragma unroll
    for (int i = 0; i < 4; i++) {
        int qrow = ty * 4 + i;
        size_t base = ((size_t)(n * S + qrow) * H + h) * D + tx * 4;
        float o0 = lo32(acc[i][0]), o1 = hi32(acc[i][0]);
        float o2 = lo32(acc[i][1]), o3 = hi32(acc[i][1]);
        __nv_bfloat16 h0 = __float2bfloat16(o0), h1 = __float2bfloat16(o1);
        __nv_bfloat16 h2 = __float2bfloat16(o2), h3 = __float2bfloat16(o3);
        *(__nv_bfloat162*)(ohi + base)     = __nv_bfloat162(h0, h1);
        *(__nv_bfloat162*)(ohi + base + 2) = __nv_bfloat162(h2, h3);
        *(__nv_bfloat162*)(olo + base) = __nv_bfloat162(
            __float2bfloat16(o0 - __bfloat162float(h0)),
            __float2bfloat16(o1 - __bfloat162float(h1)));
        *(__nv_bfloat162*)(olo + base + 2) = __nv_bfloat162(
            __float2bfloat16(o2 - __bfloat162float(h2)),
            __float2bfloat16(o3 - __bfloat162float(h3)));
    }
}

// ---------------------------------------------------------------------------
extern "C" void kernel_launch(void* const* d_in, const int* in_sizes, int n_in,
                              void* d_out, int out_size) {
    const float* x    = (const float*)d_in[0];
    const float* g_n  = (const float*)d_in[1];
    const float* b_n  = (const float*)d_in[2];
    const float* Wq   = (const float*)d_in[3];
    const float* Wk   = (const float*)d_in[4];
    const float* Wv   = (const float*)d_in[5];
    const float* Wo   = (const float*)d_in[6];
    const float* bo   = (const float*)d_in[7];
    const float* g_pe = (const float*)d_in[8];
    const float* b_pe = (const float*)d_in[9];
    const float* g0   = (const float*)d_in[10];
    const float* b0   = (const float*)d_in[11];
    const float* W0   = (const float*)d_in[12];
    const float* g1   = (const float*)d_in[13];
    const float* b1   = (const float*)d_in[14];
    const float* W1   = (const float*)d_in[15];
    float* out = (float*)d_out;

    float *v, *e, *x1, *t2, *psum, *psq, *sc, *sh, *scpe, *shpe;
    __nv_bfloat16 *ahi, *alo, *whi, *wlo, *qhi, *qlo, *khi, *klo, *ohi, *olo;
    cudaGetSymbolAddress((void**)&v,    g_v);
    cudaGetSymbolAddress((void**)&e,    g_e);
    cudaGetSymbolAddress((void**)&x1,   g_x1);
    cudaGetSymbolAddress((void**)&t2,   g_t2);
    cudaGetSymbolAddress((void**)&psum, g_psum);
    cudaGetSymbolAddress((void**)&psq,  g_psq);
    cudaGetSymbolAddress((void**)&sc,   g_scale);
    cudaGetSymbolAddress((void**)&sh,   g_shift);
    cudaGetSymbolAddress((void**)&scpe, g_scale_pe);
    cudaGetSymbolAddress((void**)&shpe, g_shift_pe);
    cudaGetSymbolAddress((void**)&ahi,  g_ahi);
    cudaGetSymbolAddress((void**)&alo,  g_alo);
    cudaGetSymbolAddress((void**)&whi,  g_whi);
    cudaGetSymbolAddress((void**)&wlo,  g_wlo);
    cudaGetSymbolAddress((void**)&qhi,  g_qhi);
    cudaGetSymbolAddress((void**)&qlo,  g_qlo);
    cudaGetSymbolAddress((void**)&khi,  g_khi);
    cudaGetSymbolAddress((void**)&klo,  g_klo);
    cudaGetSymbolAddress((void**)&ohi,  g_ohi);
    cudaGetSymbolAddress((void**)&olo,  g_olo);

    cudaFuncSetAttribute(mma_gemm<false,false,true >, cudaFuncAttributeMaxDynamicSharedMemorySize, MMA_SMEM);
    cudaFuncSetAttribute(mma_gemm<false,false,false>, cudaFuncAttributeMaxDynamicSharedMemorySize, MMA_SMEM);
    cudaFuncSetAttribute(mma_gemm<true, true, false>, cudaFuncAttributeMaxDynamicSharedMemorySize, MMA_SMEM);
    cudaFuncSetAttribute(mma_gemm<false,true, false>, cudaFuncAttributeMaxDynamicSharedMemorySize, MMA_SMEM);
    cudaFuncSetAttribute(softmax_av, cudaFuncAttributeMaxDynamicSharedMemorySize, SAV_SMEM);

    // --- BN over C on x -> scale/shift; split x ---
    bn_partial<<<dim3(1, 128), 256>>>(x, C, 256, psum, psq);
    bn_finalize<<<1, 256>>>(psum, psq, C, 128, 1.f / MROWS, g_n, b_n, sc, sh);
    split_convert<true, false><<<MROWS * C / 1024, 256>>>(x, sc, sh, ahi, alo, C - 1);

    // --- q/k (split-bf16 out), v (fp32 out) ---
    dim3 gqkv(C / 128, MROWS / 128);
    split_convert<false, false><<<C * C / 1024, 256>>>(Wq, nullptr, nullptr, whi, wlo, 3);
    mma_gemm<false,false,true><<<gqkv, 256, MMA_SMEM>>>(ahi, alo, whi, wlo, nullptr, qhi, qlo, nullptr, nullptr, MROWS, C, C);
    split_convert<false, false><<<C * C / 1024, 256>>>(Wk, nullptr, nullptr, whi, wlo, 3);
    mma_gemm<false,false,true><<<gqkv, 256, MMA_SMEM>>>(ahi, alo, whi, wlo, nullptr, khi, klo, nullptr, nullptr, MROWS, C, C);
    split_convert<false, false><<<C * C / 1024, 256>>>(Wv, nullptr, nullptr, whi, wlo, 3);
    mma_gemm<false,false,false><<<gqkv, 256, MMA_SMEM>>>(ahi, alo, whi, wlo, v, nullptr, nullptr, nullptr, nullptr, MROWS, C, C);

    // --- energy (tensor) ---
    energy_mma<<<NHB, 256>>>(qhi, qlo, khi, klo, e);

    // --- BN over S*S positions on energy ---
    bn_partial<<<dim3(SSQ / 256, 8), 256>>>(e, SSQ, 256, psum, psq);
    bn_finalize<<<SSQ / 256, 256>>>(psum, psq, SSQ, 8, 1.f / NHB, g_pe, b_pe, scpe, shpe);

    // --- fused BN + softmax + AV -> split o ---
    softmax_av<<<NHB, 256, SAV_SMEM>>>(e, scpe, shpe, v, ohi, olo);

    // --- x1 = o @ Wo^T + bo + x ---
    split_convert<false, false><<<C * C / 1024, 256>>>(Wo, nullptr, nullptr, whi, wlo, 3);
    mma_gemm<true, true, false><<<gqkv, 256, MMA_SMEM>>>(ohi, olo, whi, wlo, x1, nullptr, nullptr, bo, x, MROWS, C, C);

    // --- FFN: BN0 -> relu -> W0 ---
    bn_partial<<<dim3(1, 128), 256>>>(x1, C, 256, psum, psq);
    bn_finalize<<<1, 256>>>(psum, psq, C, 128, 1.f / MROWS, g0, b0, sc, sh);
    split_convert<true, true><<<MROWS * C / 1024, 256>>>(x1, sc, sh, ahi, alo, C - 1);
    split_convert<false, false><<<C2 * C / 1024, 256>>>(W0, nullptr, nullptr, whi, wlo, 3);
    dim3 gffn0(C2 / 128, MROWS / 128);
    mma_gemm<false,false,false><<<gffn0, 256, MMA_SMEM>>>(ahi, alo, whi, wlo, t2, nullptr, nullptr, nullptr, nullptr, MROWS, C2, C);

    // --- BN1 -> relu -> W1 -> + x1 ---
    bn_partial<<<dim3(2, 128), 256>>>(t2, C2, 256, psum, psq);
    bn_finalize<<<2, 256>>>(psum, psq, C2, 128, 1.f / MROWS, g1, b1, sc, sh);
    split_convert<true, true><<<MROWS * C2 / 1024, 256>>>(t2, sc, sh, ahi, alo, C2 - 1);
    split_convert<false, false><<<C * C2 / 1024, 256>>>(W1, nullptr, nullptr, whi, wlo, 3);
    mma_gemm<false, true, false><<<gqkv, 256, MMA_SMEM>>>(ahi, alo, whi, wlo, out, nullptr, nullptr, nullptr, x1, MROWS, C, C2);
}